// round 15
// baseline (speedup 1.0000x reference)
#include <cuda_runtime.h>
#include <cuda_bf16.h>
#include <cuda_fp16.h>
#include <cstdint>

// Problem constants (fixed shapes)
#define BB    2
#define NN    20000
#define EE    200000
#define INF   256
#define OUTF  32
#define HEADS 4
#define HDIM  (OUTF * HEADS)   // 128
#define NEG_SLOPE 0.2f
#define NROWS (BB * NN)        // 40000

// ---------------- device scratch ----------------
// CRITICAL: symbols are ONLY referenced inside device code (host-side decay of
// __device__ symbols is the GB300 ATS silent-corruption trap from rounds 1-6).
__device__ float  g_wf [HDIM * INF];                // W tf32 bits, FRAGMENT-SWIZZLED
__device__ float  g_af [2 * OUTF];                  // a (fp32)
__device__ __half g_h  [(size_t)NROWS * HDIM];      // h = x@W^T (fp16)
__device__ float  g_ssrc[(size_t)NROWS * HEADS];    // per-node src score (fp32)
__device__ float  g_sdst[(size_t)NROWS * HEADS];    // per-node dst score (fp32)
__device__ float  g_aw [(size_t)NROWS * HEADS];     // aw * 0.25
__device__ int    g_last[NN];
__device__ int    g_src [EE];
__device__ int    g_dst [EE];
__device__ int    g_cnt [NN];                       // per-src degree
__device__ int    g_rowptr[NN + 1];                 // CSR offsets
__device__ int    g_cursor[NN];                     // scatter cursors
__device__ int    g_csr [EE];                       // CSR dst values
__device__ int    g_bad_int;
__device__ int    g_odd_nonzero;
__device__ int    g_is_bf16;

__device__ __forceinline__ uint32_t f2tf32(float f) {
    uint32_t r;
    asm("cvt.rna.tf32.f32 %0, %1;" : "=r"(r) : "f"(f));
    return r;
}

#define CP_ASYNC16(smem_u32, gptr) \
    asm volatile("cp.async.cg.shared.global [%0], [%1], 16;" \
                 :: "r"(smem_u32), "l"(gptr))
#define CP_COMMIT()  asm volatile("cp.async.commit_group;" ::: "memory")
#define CP_WAIT(n)   asm volatile("cp.async.wait_group %0;" :: "n"(n) : "memory")

// ---------------- kernel 1: init + both dtype probes (fused) ---------------
__global__ void init_probe_kernel(const unsigned* __restrict__ xw,
                                  const int* __restrict__ ew) {
    int gid = blockIdx.x * blockDim.x + threadIdx.x;
    if (gid < NN) { g_last[gid] = -1; g_cnt[gid] = 0; }

    if (blockIdx.x == 0) {
        bool all_ok = true;
        for (int j = 0; j < 16; j++) {
            unsigned v = xw[threadIdx.x * 16 + j];
            unsigned lo = v & 0xFFFFu, hi = v >> 16;
            unsigned el = (lo >> 7) & 0xFF, eh = (hi >> 7) & 0xFF;
            bool okl = (lo & 0x7FFF) == 0 || (el >= 100 && el <= 140);
            bool okh = (hi & 0x7FFF) == 0 || (eh >= 100 && eh <= 140);
            all_ok &= (okl && okh);
        }
        int cnt = __syncthreads_count(all_ok);
        if (threadIdx.x == 0) g_is_bf16 = (cnt > 128) ? 1 : 0;
    } else if (blockIdx.x == 1) {
        bool bad = false, oddnz = false;
        for (int j = 0; j < 16; j++) {
            int i = threadIdx.x * 16 + j;
            int v = ew[i];
            if (v < 0 || v >= NN)  bad = true;
            if ((i & 1) && v != 0) oddnz = true;
        }
        int cbad = __syncthreads_count(bad);
        int codd = __syncthreads_count(oddnz);
        if (threadIdx.x == 0) {
            g_bad_int     = (cbad > 0) ? 1 : 0;
            g_odd_nonzero = (codd > 0) ? 1 : 0;
        }
    }
}

// ---------------- kernel 2: materialize W (tf32, fragment-swizzled) + a ----
__global__ void fconv_all_kernel(const void* __restrict__ Wraw,
                                 const void* __restrict__ araw) {
    int i = blockIdx.x * blockDim.x + threadIdx.x;
    bool bf = (g_is_bf16 != 0);
    if (i < HDIM * INF) {
        float v = bf ? __bfloat162float(((const __nv_bfloat16*)Wraw)[i])
                     : ((const float*)Wraw)[i];
        int n = i >> 8, k = i & 255;
        int n_blk = n >> 3, g = n & 7;
        int kstep = k >> 3, t = k & 3, h2 = (k >> 2) & 1;
        int dst = ((n_blk * 32 + kstep) * 32 + g * 4 + t) * 2 + h2;
        g_wf[dst] = __uint_as_float(f2tf32(v));
    } else if (i < HDIM * INF + 2 * OUTF) {
        int j = i - HDIM * INF;
        float v = bf ? __bfloat162float(((const __nv_bfloat16*)araw)[j])
                     : ((const float*)araw)[j];
        g_af[j] = v;
    }
}

// ---------------- kernel 3: convert + last-edge + degree histogram ---------
__global__ void convert_lastedge_kernel(const void* __restrict__ raw) {
    int e = blockIdx.x * blockDim.x + threadIdx.x;
    if (e >= EE) return;
    int s, d;
    if (g_bad_int) {                 // float32 layout
        const float* p = (const float*)raw;
        s = (int)p[e];  d = (int)p[EE + e];
    } else if (g_odd_nonzero) {      // int32 layout
        const int* p = (const int*)raw;
        s = p[e];       d = p[EE + e];
    } else {                         // int64 layout
        const long long* p = (const long long*)raw;
        s = (int)p[e];  d = (int)p[EE + e];
    }
    s = min(max(s, 0), NN - 1);
    d = min(max(d, 0), NN - 1);
    g_src[e] = s;
    g_dst[e] = d;
    atomicMax(&g_last[s], e);
    atomicAdd(&g_cnt[s], 1);
}

// ---------------- kernel 4: 4-stage BK=8 tf32 GEMM (unchanged R14) ---------
#define BM 128
#define BK 8
#define NSTAGE 4
#define AST8 12
__global__ __launch_bounds__(256, 2) void gemm_tf32(const void* __restrict__ xraw) {
    __shared__ float  As[NSTAGE][BM * AST8];
    __shared__ float2 Bs[NSTAGE][512];

    const int tid  = threadIdx.x;
    const int lane = tid & 31;
    const int g    = lane >> 2;
    const int t    = lane & 3;
    const int warp = tid >> 5;
    const int wm   = warp & 3;
    const int wn   = warp >> 2;
    const int m0   = blockIdx.x * BM;
    const bool is_bf16 = (g_is_bf16 != 0);

    const float2* gw = (const float2*)g_wf;

    float acc[2][8][4];
    #pragma unroll
    for (int i = 0; i < 2; i++)
        #pragma unroll
        for (int j = 0; j < 8; j++)
            #pragma unroll
            for (int q = 0; q < 4; q++) acc[i][j][q] = 0.0f;

    auto issue_tile = [&](int kstep, int buf) {
        {
            int nb  = tid >> 4;
            int c16 = tid & 15;
            uint32_t d = (uint32_t)__cvta_generic_to_shared(
                &Bs[buf][nb * 32 + c16 * 2]);
            CP_ASYNC16(d, gw + ((size_t)(nb * 32 + kstep)) * 32 + c16 * 2);
        }
        if (!is_bf16) {
            int r = tid >> 1;
            int c = (tid & 1) * 4;
            int row = min(m0 + r, NROWS - 1);
            uint32_t d = (uint32_t)__cvta_generic_to_shared(
                &As[buf][r * AST8 + c]);
            CP_ASYNC16(d, (const float*)xraw + (size_t)row * INF + kstep * 8 + c);
        } else {
            if (tid < BM) {
                int row = min(m0 + tid, NROWS - 1);
                uint4 u = *(const uint4*)((const __nv_bfloat16*)xraw +
                                          (size_t)row * INF + kstep * 8);
                const __nv_bfloat162* hb = (const __nv_bfloat162*)&u;
                float* dstp = &As[buf][tid * AST8];
                #pragma unroll
                for (int j = 0; j < 4; j++) {
                    float2 f = __bfloat1622float2(hb[j]);
                    dstp[2 * j]     = f.x;
                    dstp[2 * j + 1] = f.y;
                }
            }
        }
        CP_COMMIT();
    };

    issue_tile(0, 0);
    issue_tile(1, 1);
    issue_tile(2, 2);

    #pragma unroll 4
    for (int i = 0; i < INF / BK; i++) {
        CP_WAIT(2);
        __syncthreads();
        if (i + 3 < INF / BK) issue_tile(i + 3, (i + 3) & (NSTAGE - 1));

        int buf = i & (NSTAGE - 1);
        uint32_t a[2][4];
        #pragma unroll
        for (int mq = 0; mq < 2; mq++) {
            const float* ap = &As[buf][(wm * 32 + mq * 16 + g) * AST8 + t];
            a[mq][0] = f2tf32(ap[0]);
            a[mq][1] = f2tf32(ap[8 * AST8]);
            a[mq][2] = f2tf32(ap[4]);
            a[mq][3] = f2tf32(ap[8 * AST8 + 4]);
        }
        #pragma unroll
        for (int nt = 0; nt < 8; nt++) {
            float2 bb = Bs[buf][(wn * 8 + nt) * 32 + lane];
            uint32_t b0 = __float_as_uint(bb.x);
            uint32_t b1 = __float_as_uint(bb.y);
            #pragma unroll
            for (int mq = 0; mq < 2; mq++) {
                asm volatile(
                    "mma.sync.aligned.m16n8k8.row.col.f32.tf32.tf32.f32 "
                    "{%0,%1,%2,%3}, {%4,%5,%6,%7}, {%8,%9}, {%0,%1,%2,%3};"
                    : "+f"(acc[mq][nt][0]), "+f"(acc[mq][nt][1]),
                      "+f"(acc[mq][nt][2]), "+f"(acc[mq][nt][3])
                    : "r"(a[mq][0]), "r"(a[mq][1]), "r"(a[mq][2]),
                      "r"(a[mq][3]), "r"(b0), "r"(b1));
            }
        }
        __syncthreads();
    }

    float ss[2][4], sd[2][4];
    #pragma unroll
    for (int i = 0; i < 2; i++)
        #pragma unroll
        for (int j = 0; j < 4; j++) { ss[i][j] = 0.f; sd[i][j] = 0.f; }

    #pragma unroll
    for (int mq = 0; mq < 2; mq++) {
        int mrow = m0 + wm * 32 + mq * 16 + g;
        #pragma unroll
        for (int nt = 0; nt < 8; nt++) {
            int hl = nt >> 2;
            int fl = (nt & 3) * 8 + 2 * t;
            int ncol = wn * 64 + nt * 8 + 2 * t;
            if (mrow < NROWS)
                *(__half2*)&g_h[(size_t)mrow * HDIM + ncol] =
                    __floats2half2_rn(acc[mq][nt][0], acc[mq][nt][1]);
            if (mrow + 8 < NROWS)
                *(__half2*)&g_h[(size_t)(mrow + 8) * HDIM + ncol] =
                    __floats2half2_rn(acc[mq][nt][2], acc[mq][nt][3]);
            float a0s = g_af[fl],        a1s = g_af[fl + 1];
            float a0d = g_af[OUTF + fl], a1d = g_af[OUTF + fl + 1];
            ss[hl][mq*2+0] += acc[mq][nt][0] * a0s + acc[mq][nt][1] * a1s;
            ss[hl][mq*2+1] += acc[mq][nt][2] * a0s + acc[mq][nt][3] * a1s;
            sd[hl][mq*2+0] += acc[mq][nt][0] * a0d + acc[mq][nt][1] * a1d;
            sd[hl][mq*2+1] += acc[mq][nt][2] * a0d + acc[mq][nt][3] * a1d;
        }
    }
    #pragma unroll
    for (int off = 1; off < 4; off <<= 1) {
        #pragma unroll
        for (int i = 0; i < 2; i++)
            #pragma unroll
            for (int j = 0; j < 4; j++) {
                ss[i][j] += __shfl_xor_sync(0xffffffffu, ss[i][j], off);
                sd[i][j] += __shfl_xor_sync(0xffffffffu, sd[i][j], off);
            }
    }
    if (t == 0) {
        #pragma unroll
        for (int hl = 0; hl < 2; hl++) {
            int head = wn * 2 + hl;
            #pragma unroll
            for (int mq = 0; mq < 2; mq++)
                #pragma unroll
                for (int rr = 0; rr < 2; rr++) {
                    int row = m0 + wm * 32 + mq * 16 + g + rr * 8;
                    if (row < NROWS) {
                        g_ssrc[row * HEADS + head] = ss[hl][mq*2+rr];
                        g_sdst[row * HEADS + head] = sd[hl][mq*2+rr];
                    }
                }
        }
    }
}

// ---------------- kernel 5: CSR exclusive scan (1 block, 1024 threads) -----
__global__ void scan_kernel() {
    __shared__ int sums[1024];
    int t = threadIdx.x;
    int base = t * 20;                 // 1024*20 = 20480 >= NN
    int local[20];
    int run = 0;
    #pragma unroll
    for (int j = 0; j < 20; j++) {
        int idx = base + j;
        int c = (idx < NN) ? g_cnt[idx] : 0;
        local[j] = run;
        run += c;
    }
    sums[t] = run;
    __syncthreads();
    for (int off = 1; off < 1024; off <<= 1) {
        int v = (t >= off) ? sums[t - off] : 0;
        __syncthreads();
        sums[t] += v;
        __syncthreads();
    }
    int pre = (t > 0) ? sums[t - 1] : 0;
    #pragma unroll
    for (int j = 0; j < 20; j++) {
        int idx = base + j;
        if (idx < NN) {
            g_rowptr[idx] = pre + local[j];
            g_cursor[idx] = pre + local[j];
        }
    }
    if (t == 1023) g_rowptr[NN] = sums[1023];
}

// ---------------- kernel 6: CSR scatter ------------------------------------
__global__ void scatter_kernel() {
    int e = blockIdx.x * blockDim.x + threadIdx.x;
    if (e >= EE) return;
    int s = g_src[e];
    int pos = atomicAdd(&g_cursor[s], 1);
    g_csr[pos] = g_dst[e];
}

// ---------------- kernel 7: aw from last-edge softmax over batch -----------
__global__ void aw_kernel() {
    int gid = blockIdx.x * blockDim.x + threadIdx.x;
    if (gid >= NN * HEADS) return;
    int hh = gid & (HEADS - 1);
    int n  = gid >> 2;
    int e  = g_last[n];
    float w0 = 0.0f, w1 = 0.0f;
    if (e >= 0) {
        int d = g_dst[e];
        float z0 = g_ssrc[n * HEADS + hh]        + g_sdst[d * HEADS + hh];
        float z1 = g_ssrc[(NN + n) * HEADS + hh] + g_sdst[(NN + d) * HEADS + hh];
        z0 = z0 > 0.0f ? z0 : NEG_SLOPE * z0;
        z1 = z1 > 0.0f ? z1 : NEG_SLOPE * z1;
        float m  = fmaxf(z0, z1);
        float p0 = __expf(z0 - m);
        float p1 = __expf(z1 - m);
        float inv = 1.0f / (p0 + p1);
        w0 = p0 * inv;
        w1 = p1 * inv;
    }
    g_aw[n * HEADS + hh]        = 0.25f * w0;   // fold head-mean
    g_aw[(NN + n) * HEADS + hh] = 0.25f * w1;
}

// ---------------- kernel 8: CSR aggregation — gather only, no atomics ------
// One warp per (node, batch). Lane i reads halves 4i..4i+3 of each dst row
// (head = i>>3, fs = (i&7)*4 ..+3). Sum rows over edges, scale by aw[head]
// once, butterfly-reduce heads (xor 8, 16), lanes 0..7 write the 128B row.
__global__ __launch_bounds__(256) void agg_csr_kernel(float* __restrict__ out) {
    int wid  = blockIdx.x * 8 + (threadIdx.x >> 5);
    if (wid >= NROWS) return;
    int lane = threadIdx.x & 31;
    int n = wid >> 1;
    int b = wid & 1;

    int beg = g_rowptr[n];
    int end = g_rowptr[n + 1];

    const __half* hbase = g_h + (size_t)b * NN * HDIM;
    float a0 = 0.f, a1 = 0.f, a2 = 0.f, a3 = 0.f;

    int j = beg;
    // unroll-by-2 for MLP
    for (; j + 1 < end; j += 2) {
        int d0 = g_csr[j];
        int d1 = g_csr[j + 1];
        uint2 u0 = __ldg((const uint2*)(hbase + (size_t)d0 * HDIM) + lane);
        uint2 u1 = __ldg((const uint2*)(hbase + (size_t)d1 * HDIM) + lane);
        float2 p0 = __half22float2(*(__half2*)&u0.x);
        float2 q0 = __half22float2(*(__half2*)&u0.y);
        float2 p1 = __half22float2(*(__half2*)&u1.x);
        float2 q1 = __half22float2(*(__half2*)&u1.y);
        a0 += p0.x + p1.x;  a1 += p0.y + p1.y;
        a2 += q0.x + q1.x;  a3 += q0.y + q1.y;
    }
    if (j < end) {
        int d0 = g_csr[j];
        uint2 u0 = __ldg((const uint2*)(hbase + (size_t)d0 * HDIM) + lane);
        float2 p0 = __half22float2(*(__half2*)&u0.x);
        float2 q0 = __half22float2(*(__half2*)&u0.y);
        a0 += p0.x;  a1 += p0.y;  a2 += q0.x;  a3 += q0.y;
    }

    int head = lane >> 3;
    float c = g_aw[((size_t)b * NN + n) * HEADS + head];   // includes 0.25
    a0 *= c;  a1 *= c;  a2 *= c;  a3 *= c;

    #pragma unroll
    for (int off = 8; off <= 16; off <<= 1) {
        a0 += __shfl_xor_sync(0xffffffffu, a0, off);
        a1 += __shfl_xor_sync(0xffffffffu, a1, off);
        a2 += __shfl_xor_sync(0xffffffffu, a2, off);
        a3 += __shfl_xor_sync(0xffffffffu, a3, off);
    }
    if (lane < 8) {
        *(float4*)&out[((size_t)b * NN + n) * OUTF + lane * 4] =
            make_float4(a0, a1, a2, a3);
    }
}

// ---------------- launch ---------------------------------------------------
extern "C" void kernel_launch(void* const* d_in, const int* in_sizes, int n_in,
                              void* d_out, int out_size) {
    // Rank-based binding: largest -> x, 2nd -> edges, 3rd -> W, smallest -> a
    int order[8];
    int m = n_in < 8 ? n_in : 8;
    for (int i = 0; i < m; i++) order[i] = i;
    for (int i = 0; i < m; i++)
        for (int j = i + 1; j < m; j++)
            if (in_sizes[order[j]] > in_sizes[order[i]]) {
                int t = order[i]; order[i] = order[j]; order[j] = t;
            }
    const void* x  = d_in[m > 0 ? order[0] : 0];
    const void* ei = d_in[m > 1 ? order[1] : 1];
    const void* W  = d_in[m > 2 ? order[2] : 2];
    const void* a  = d_in[m > 3 ? order[3] : 3];

    float* out = (float*)d_out;

    init_probe_kernel<<<(NN + 255) / 256, 256>>>((const unsigned*)x,
                                                 (const int*)ei);         // 1
    fconv_all_kernel<<<(HDIM * INF + 2 * OUTF + 255) / 256, 256>>>(W, a); // 2
    convert_lastedge_kernel<<<(EE + 255) / 256, 256>>>(ei);               // 3
    gemm_tf32<<<(NROWS + BM - 1) / BM, 256>>>(x);                         // 4 <- profiled
    scan_kernel<<<1, 1024>>>();                                           // 5
    scatter_kernel<<<(EE + 255) / 256, 256>>>();                          // 6
    aw_kernel<<<(NN * HEADS + 255) / 256, 256>>>();                       // 7
    agg_csr_kernel<<<(NROWS + 7) / 8, 256>>>(out);                        // 8
}

// round 16
// speedup vs baseline: 1.5069x; 1.5069x over previous
#include <cuda_runtime.h>
#include <cuda_bf16.h>
#include <cuda_fp16.h>
#include <cstdint>

// Problem constants (fixed shapes)
#define BB    2
#define NN    20000
#define EE    200000
#define INF   256
#define OUTF  32
#define HEADS 4
#define HDIM  (OUTF * HEADS)   // 128
#define NEG_SLOPE 0.2f
#define NROWS (BB * NN)        // 40000

// ---------------- device scratch ----------------
// CRITICAL: symbols are ONLY referenced inside device code (host-side decay of
// __device__ symbols is the GB300 ATS silent-corruption trap from rounds 1-6).
__device__ float  g_wf [HDIM * INF];                // W tf32 bits, FRAGMENT-SWIZZLED
__device__ float  g_af [2 * OUTF];                  // a (fp32)
__device__ __half g_h  [(size_t)NROWS * HDIM];      // h = x@W^T (fp16)
__device__ float  g_ssrc[(size_t)NROWS * HEADS];    // per-node src score (fp32)
__device__ float  g_sdst[(size_t)NROWS * HEADS];    // per-node dst score (fp32)
__device__ float  g_aw [(size_t)NROWS * HEADS];     // aw * 0.25
__device__ int    g_last[NN];
__device__ int    g_src [EE];
__device__ int    g_dst [EE];
__device__ int    g_bad_int;
__device__ int    g_odd_nonzero;
__device__ int    g_is_bf16;

__device__ __forceinline__ uint32_t f2tf32(float f) {
    uint32_t r;
    asm("cvt.rna.tf32.f32 %0, %1;" : "=r"(r) : "f"(f));
    return r;
}

#define CP_ASYNC16(smem_u32, gptr) \
    asm volatile("cp.async.cg.shared.global [%0], [%1], 16;" \
                 :: "r"(smem_u32), "l"(gptr))
#define CP_COMMIT()  asm volatile("cp.async.commit_group;" ::: "memory")
#define CP_WAIT(n)   asm volatile("cp.async.wait_group %0;" :: "n"(n) : "memory")

// ---------------- kernel 1: init (zero out) + dtype probes -----------------
__global__ void init_probe_kernel(float* __restrict__ out, int out_size,
                                  const unsigned* __restrict__ xw,
                                  const int* __restrict__ ew) {
    int gid = blockIdx.x * blockDim.x + threadIdx.x;
    if (gid < out_size) out[gid] = 0.0f;
    if (gid < NN)       g_last[gid] = -1;

    if (blockIdx.x == 0) {
        bool all_ok = true;
        for (int j = 0; j < 16; j++) {
            unsigned v = xw[threadIdx.x * 16 + j];
            unsigned lo = v & 0xFFFFu, hi = v >> 16;
            unsigned el = (lo >> 7) & 0xFF, eh = (hi >> 7) & 0xFF;
            bool okl = (lo & 0x7FFF) == 0 || (el >= 100 && el <= 140);
            bool okh = (hi & 0x7FFF) == 0 || (eh >= 100 && eh <= 140);
            all_ok &= (okl && okh);
        }
        int cnt = __syncthreads_count(all_ok);
        if (threadIdx.x == 0) g_is_bf16 = (cnt > 128) ? 1 : 0;
    } else if (blockIdx.x == 1) {
        bool bad = false, oddnz = false;
        for (int j = 0; j < 16; j++) {
            int i = threadIdx.x * 16 + j;
            int v = ew[i];
            if (v < 0 || v >= NN)  bad = true;
            if ((i & 1) && v != 0) oddnz = true;
        }
        int cbad = __syncthreads_count(bad);
        int codd = __syncthreads_count(oddnz);
        if (threadIdx.x == 0) {
            g_bad_int     = (cbad > 0) ? 1 : 0;
            g_odd_nonzero = (codd > 0) ? 1 : 0;
        }
    }
}

// ---------------- kernel 2: materialize W (tf32, fragment-swizzled) + a ----
// For W[n][k]: n_blk=n>>3, g=n&7, kstep=k>>3, t=k&3, h2=(k>>2)&1
//   g_wf[ ((n_blk*32 + kstep)*32 + g*4 + t)*2 + h2 ] = tf32(W[n][k])
__global__ void fconv_all_kernel(const void* __restrict__ Wraw,
                                 const void* __restrict__ araw) {
    int i = blockIdx.x * blockDim.x + threadIdx.x;
    bool bf = (g_is_bf16 != 0);
    if (i < HDIM * INF) {
        float v = bf ? __bfloat162float(((const __nv_bfloat16*)Wraw)[i])
                     : ((const float*)Wraw)[i];
        int n = i >> 8, k = i & 255;
        int n_blk = n >> 3, g = n & 7;
        int kstep = k >> 3, t = k & 3, h2 = (k >> 2) & 1;
        int dst = ((n_blk * 32 + kstep) * 32 + g * 4 + t) * 2 + h2;
        g_wf[dst] = __uint_as_float(f2tf32(v));
    } else if (i < HDIM * INF + 2 * OUTF) {
        int j = i - HDIM * INF;
        float v = bf ? __bfloat162float(((const __nv_bfloat16*)araw)[j])
                     : ((const float*)araw)[j];
        g_af[j] = v;
    }
}

// ---------------- kernel 3: convert indices + last-edge (fused) ------------
__global__ void convert_lastedge_kernel(const void* __restrict__ raw) {
    int e = blockIdx.x * blockDim.x + threadIdx.x;
    if (e >= EE) return;
    int s, d;
    if (g_bad_int) {                 // float32 layout
        const float* p = (const float*)raw;
        s = (int)p[e];  d = (int)p[EE + e];
    } else if (g_odd_nonzero) {      // int32 layout
        const int* p = (const int*)raw;
        s = p[e];       d = p[EE + e];
    } else {                         // int64 layout
        const long long* p = (const long long*)raw;
        s = (int)p[e];  d = (int)p[EE + e];
    }
    s = min(max(s, 0), NN - 1);
    d = min(max(d, 0), NN - 1);
    g_src[e] = s;
    g_dst[e] = d;
    atomicMax(&g_last[s], e);
}

// ---------------- kernel 4: 4-stage BK=8 tf32 GEMM, single barrier/iter ----
// BM=128 x BN=128 per block, grid 313. wait_group 2 -> 3 tiles in flight.
// The tile written at iteration i is buffer (i-1)&3, whose readers all passed
// this iteration's TOP barrier -> no trailing barrier needed.
#define BM 128
#define BK 8
#define NSTAGE 4
#define AST8 12   // (12g+t) mod 32 bijective over warp -> conflict-free LDS
__global__ __launch_bounds__(256, 2) void gemm_tf32(const void* __restrict__ xraw) {
    __shared__ float  As[NSTAGE][BM * AST8];   // 4 x 6144 B
    __shared__ float2 Bs[NSTAGE][512];         // 4 x 4096 B  (total 40 KB)

    const int tid  = threadIdx.x;
    const int lane = tid & 31;
    const int g    = lane >> 2;
    const int t    = lane & 3;
    const int warp = tid >> 5;
    const int wm   = warp & 3;         // 32-row band
    const int wn   = warp >> 2;        // 64-col half
    const int m0   = blockIdx.x * BM;
    const bool is_bf16 = (g_is_bf16 != 0);

    const float2* gw = (const float2*)g_wf;

    float acc[2][8][4];
    #pragma unroll
    for (int i = 0; i < 2; i++)
        #pragma unroll
        for (int j = 0; j < 8; j++)
            #pragma unroll
            for (int q = 0; q < 4; q++) acc[i][j][q] = 0.0f;

    auto issue_tile = [&](int kstep, int buf) {
        {
            int nb  = tid >> 4;            // 0..15
            int c16 = tid & 15;
            uint32_t d = (uint32_t)__cvta_generic_to_shared(
                &Bs[buf][nb * 32 + c16 * 2]);
            CP_ASYNC16(d, gw + ((size_t)(nb * 32 + kstep)) * 32 + c16 * 2);
        }
        if (!is_bf16) {
            int r = tid >> 1;
            int c = (tid & 1) * 4;
            int row = min(m0 + r, NROWS - 1);
            uint32_t d = (uint32_t)__cvta_generic_to_shared(
                &As[buf][r * AST8 + c]);
            CP_ASYNC16(d, (const float*)xraw + (size_t)row * INF + kstep * 8 + c);
        } else {
            if (tid < BM) {
                int row = min(m0 + tid, NROWS - 1);
                uint4 u = *(const uint4*)((const __nv_bfloat16*)xraw +
                                          (size_t)row * INF + kstep * 8);
                const __nv_bfloat162* hb = (const __nv_bfloat162*)&u;
                float* dstp = &As[buf][tid * AST8];
                #pragma unroll
                for (int j = 0; j < 4; j++) {
                    float2 f = __bfloat1622float2(hb[j]);
                    dstp[2 * j]     = f.x;
                    dstp[2 * j + 1] = f.y;
                }
            }
        }
        CP_COMMIT();
    };

    issue_tile(0, 0);
    issue_tile(1, 1);
    issue_tile(2, 2);

    #pragma unroll 4
    for (int i = 0; i < INF / BK; i++) {      // 32 iterations
        CP_WAIT(2);                           // tile i resident
        __syncthreads();                      // visibility + write-safety barrier
        if (i + 3 < INF / BK) issue_tile(i + 3, (i + 3) & (NSTAGE - 1));

        int buf = i & (NSTAGE - 1);
        uint32_t a[2][4];
        #pragma unroll
        for (int mq = 0; mq < 2; mq++) {
            const float* ap = &As[buf][(wm * 32 + mq * 16 + g) * AST8 + t];
            a[mq][0] = f2tf32(ap[0]);
            a[mq][1] = f2tf32(ap[8 * AST8]);
            a[mq][2] = f2tf32(ap[4]);
            a[mq][3] = f2tf32(ap[8 * AST8 + 4]);
        }
        #pragma unroll
        for (int nt = 0; nt < 8; nt++) {
            float2 bb = Bs[buf][(wn * 8 + nt) * 32 + lane];
            uint32_t b0 = __float_as_uint(bb.x);
            uint32_t b1 = __float_as_uint(bb.y);
            #pragma unroll
            for (int mq = 0; mq < 2; mq++) {
                asm volatile(
                    "mma.sync.aligned.m16n8k8.row.col.f32.tf32.tf32.f32 "
                    "{%0,%1,%2,%3}, {%4,%5,%6,%7}, {%8,%9}, {%0,%1,%2,%3};"
                    : "+f"(acc[mq][nt][0]), "+f"(acc[mq][nt][1]),
                      "+f"(acc[mq][nt][2]), "+f"(acc[mq][nt][3])
                    : "r"(a[mq][0]), "r"(a[mq][1]), "r"(a[mq][2]),
                      "r"(a[mq][3]), "r"(b0), "r"(b1));
            }
        }
        // no trailing barrier: next write target is (i+4)&3, readers already
        // synchronized by the next iteration's top barrier.
    }

    // Epilogue: fp16 h + fused score dots.
    float ss[2][4], sd[2][4];   // [local head][mq*2 + (0:row g, 1:row g+8)]
    #pragma unroll
    for (int i = 0; i < 2; i++)
        #pragma unroll
        for (int j = 0; j < 4; j++) { ss[i][j] = 0.f; sd[i][j] = 0.f; }

    #pragma unroll
    for (int mq = 0; mq < 2; mq++) {
        int mrow = m0 + wm * 32 + mq * 16 + g;
        #pragma unroll
        for (int nt = 0; nt < 8; nt++) {
            int hl = nt >> 2;
            int fl = (nt & 3) * 8 + 2 * t;
            int ncol = wn * 64 + nt * 8 + 2 * t;
            if (mrow < NROWS)
                *(__half2*)&g_h[(size_t)mrow * HDIM + ncol] =
                    __floats2half2_rn(acc[mq][nt][0], acc[mq][nt][1]);
            if (mrow + 8 < NROWS)
                *(__half2*)&g_h[(size_t)(mrow + 8) * HDIM + ncol] =
                    __floats2half2_rn(acc[mq][nt][2], acc[mq][nt][3]);
            float a0s = g_af[fl],        a1s = g_af[fl + 1];
            float a0d = g_af[OUTF + fl], a1d = g_af[OUTF + fl + 1];
            ss[hl][mq*2+0] += acc[mq][nt][0] * a0s + acc[mq][nt][1] * a1s;
            ss[hl][mq*2+1] += acc[mq][nt][2] * a0s + acc[mq][nt][3] * a1s;
            sd[hl][mq*2+0] += acc[mq][nt][0] * a0d + acc[mq][nt][1] * a1d;
            sd[hl][mq*2+1] += acc[mq][nt][2] * a0d + acc[mq][nt][3] * a1d;
        }
    }
    #pragma unroll
    for (int off = 1; off < 4; off <<= 1) {
        #pragma unroll
        for (int i = 0; i < 2; i++)
            #pragma unroll
            for (int j = 0; j < 4; j++) {
                ss[i][j] += __shfl_xor_sync(0xffffffffu, ss[i][j], off);
                sd[i][j] += __shfl_xor_sync(0xffffffffu, sd[i][j], off);
            }
    }
    if (t == 0) {
        #pragma unroll
        for (int hl = 0; hl < 2; hl++) {
            int head = wn * 2 + hl;
            #pragma unroll
            for (int mq = 0; mq < 2; mq++)
                #pragma unroll
                for (int rr = 0; rr < 2; rr++) {
                    int row = m0 + wm * 32 + mq * 16 + g + rr * 8;
                    if (row < NROWS) {
                        g_ssrc[row * HEADS + head] = ss[hl][mq*2+rr];
                        g_sdst[row * HEADS + head] = sd[hl][mq*2+rr];
                    }
                }
        }
    }
}

// ---------------- kernel 5: aw from last-edge softmax over batch -----------
__global__ void aw_kernel() {
    int gid = blockIdx.x * blockDim.x + threadIdx.x;   // n*HEADS + h
    if (gid >= NN * HEADS) return;
    int hh = gid & (HEADS - 1);
    int n  = gid >> 2;
    int e  = g_last[n];
    float w0 = 0.0f, w1 = 0.0f;
    if (e >= 0) {
        int d = g_dst[e];
        float z0 = g_ssrc[n * HEADS + hh]        + g_sdst[d * HEADS + hh];
        float z1 = g_ssrc[(NN + n) * HEADS + hh] + g_sdst[(NN + d) * HEADS + hh];
        z0 = z0 > 0.0f ? z0 : NEG_SLOPE * z0;
        z1 = z1 > 0.0f ? z1 : NEG_SLOPE * z1;
        float m  = fmaxf(z0, z1);
        float p0 = __expf(z0 - m);
        float p1 = __expf(z1 - m);
        float inv = 1.0f / (p0 + p1);
        w0 = p0 * inv;
        w1 = p1 * inv;
    }
    g_aw[n * HEADS + hh]        = 0.25f * w0;   // fold head-mean
    g_aw[(NN + n) * HEADS + hh] = 0.25f * w1;
}

// ---------------- kernel 6: aggregation, both batches per thread -----------
__device__ __forceinline__ void red_add_v4(float* ptr, float4 v) {
    asm volatile("red.global.add.v4.f32 [%0], {%1, %2, %3, %4};"
                 :: "l"(ptr), "f"(v.x), "f"(v.y), "f"(v.z), "f"(v.w)
                 : "memory");
}

__device__ __forceinline__ float4 ldh4(const __half* p) {
    uint2 u = __ldg((const uint2*)p);
    float2 a = __half22float2(*(__half2*)&u.x);
    float2 b = __half22float2(*(__half2*)&u.y);
    return make_float4(a.x, a.y, b.x, b.y);
}

__global__ __launch_bounds__(256) void agg_kernel(float* __restrict__ out) {
    int gid = blockIdx.x * blockDim.x + threadIdx.x;
    if (gid >= EE * (OUTF / 4)) return;
    int f4 = gid & 7;          // 0..7
    int e  = gid >> 3;

    int src = g_src[e];
    int dst = g_dst[e];

    float4 c0 = *(const float4*)(g_aw + (size_t)src * HEADS);
    float4 c1 = *(const float4*)(g_aw + ((size_t)NN + src) * HEADS);

    const __half* hp0 = g_h + (size_t)dst * HDIM + f4 * 4;
    const __half* hp1 = hp0 + (size_t)NN * HDIM;
    // 8 independent gathers in flight
    float4 h00 = ldh4(hp0);
    float4 h01 = ldh4(hp0 + OUTF);
    float4 h02 = ldh4(hp0 + 2 * OUTF);
    float4 h03 = ldh4(hp0 + 3 * OUTF);
    float4 h10 = ldh4(hp1);
    float4 h11 = ldh4(hp1 + OUTF);
    float4 h12 = ldh4(hp1 + 2 * OUTF);
    float4 h13 = ldh4(hp1 + 3 * OUTF);

    float4 v0, v1;
    v0.x = c0.x * h00.x + c0.y * h01.x + c0.z * h02.x + c0.w * h03.x;
    v0.y = c0.x * h00.y + c0.y * h01.y + c0.z * h02.y + c0.w * h03.y;
    v0.z = c0.x * h00.z + c0.y * h01.z + c0.z * h02.z + c0.w * h03.z;
    v0.w = c0.x * h00.w + c0.y * h01.w + c0.z * h02.w + c0.w * h03.w;
    v1.x = c1.x * h10.x + c1.y * h11.x + c1.z * h12.x + c1.w * h13.x;
    v1.y = c1.x * h10.y + c1.y * h11.y + c1.z * h12.y + c1.w * h13.y;
    v1.z = c1.x * h10.z + c1.y * h11.z + c1.z * h12.z + c1.w * h13.z;
    v1.w = c1.x * h10.w + c1.y * h11.w + c1.z * h12.w + c1.w * h13.w;

    red_add_v4(out + (size_t)src * OUTF + f4 * 4, v0);
    red_add_v4(out + ((size_t)NN + src) * OUTF + f4 * 4, v1);
}

// ---------------- launch ---------------------------------------------------
extern "C" void kernel_launch(void* const* d_in, const int* in_sizes, int n_in,
                              void* d_out, int out_size) {
    // Rank-based binding: largest -> x, 2nd -> edges, 3rd -> W, smallest -> a
    int order[8];
    int m = n_in < 8 ? n_in : 8;
    for (int i = 0; i < m; i++) order[i] = i;
    for (int i = 0; i < m; i++)
        for (int j = i + 1; j < m; j++)
            if (in_sizes[order[j]] > in_sizes[order[i]]) {
                int t = order[i]; order[i] = order[j]; order[j] = t;
            }
    const void* x  = d_in[m > 0 ? order[0] : 0];
    const void* ei = d_in[m > 1 ? order[1] : 1];
    const void* W  = d_in[m > 2 ? order[2] : 2];
    const void* a  = d_in[m > 3 ? order[3] : 3];

    float* out = (float*)d_out;

    {
        int n = out_size > NN ? out_size : NN;
        init_probe_kernel<<<(n + 255) / 256, 256>>>(out, out_size,
                             (const unsigned*)x, (const int*)ei);         // 1
    }
    fconv_all_kernel<<<(HDIM * INF + 2 * OUTF + 255) / 256, 256>>>(W, a); // 2
    convert_lastedge_kernel<<<(EE + 255) / 256, 256>>>(ei);               // 3
    gemm_tf32<<<(NROWS + BM - 1) / BM, 256>>>(x);                         // 4 <- profiled
    aw_kernel<<<(NN * HEADS + 255) / 256, 256>>>();                       // 5
    agg_kernel<<<(EE * (OUTF / 4) + 255) / 256, 256>>>(out);              // 6
}

// round 17
// speedup vs baseline: 1.5542x; 1.0314x over previous
#include <cuda_runtime.h>
#include <cuda_bf16.h>
#include <cuda_fp16.h>
#include <cstdint>

// Problem constants (fixed shapes)
#define BB    2
#define NN    20000
#define EE    200000
#define INF   256
#define OUTF  32
#define HEADS 4
#define HDIM  (OUTF * HEADS)   // 128
#define NEG_SLOPE 0.2f
#define NROWS (BB * NN)        // 40000

// ---------------- device scratch ----------------
// CRITICAL: symbols are ONLY referenced inside device code (host-side decay of
// __device__ symbols is the GB300 ATS silent-corruption trap from rounds 1-6).
__device__ __half g_wh [HDIM * INF];                // W fp16, FRAGMENT-SWIZZLED
__device__ __half g_xh [(size_t)NROWS * INF];       // x fp16 (20.5 MB)
__device__ float  g_af [2 * OUTF];                  // a (fp32)
__device__ __half g_h  [(size_t)NROWS * HDIM];      // h = x@W^T (fp16)
__device__ float  g_ssrc[(size_t)NROWS * HEADS];    // per-node src score (fp32)
__device__ float  g_sdst[(size_t)NROWS * HEADS];    // per-node dst score (fp32)
__device__ float  g_aw [(size_t)NROWS * HEADS];     // aw * 0.25
__device__ int    g_last[NN];
__device__ int    g_src [EE];
__device__ int    g_dst [EE];
__device__ int    g_bad_int;
__device__ int    g_odd_nonzero;
__device__ int    g_is_bf16;

#define CP_ASYNC16(smem_u32, gptr) \
    asm volatile("cp.async.cg.shared.global [%0], [%1], 16;" \
                 :: "r"(smem_u32), "l"(gptr))
#define CP_COMMIT()  asm volatile("cp.async.commit_group;" ::: "memory")
#define CP_WAIT(n)   asm volatile("cp.async.wait_group %0;" :: "n"(n) : "memory")

// ---------------- kernel 1: init (zero out) + dtype probes -----------------
__global__ void init_probe_kernel(float* __restrict__ out, int out_size,
                                  const unsigned* __restrict__ xw,
                                  const int* __restrict__ ew) {
    int gid = blockIdx.x * blockDim.x + threadIdx.x;
    if (gid < out_size) out[gid] = 0.0f;
    if (gid < NN)       g_last[gid] = -1;

    if (blockIdx.x == 0) {
        bool all_ok = true;
        for (int j = 0; j < 16; j++) {
            unsigned v = xw[threadIdx.x * 16 + j];
            unsigned lo = v & 0xFFFFu, hi = v >> 16;
            unsigned el = (lo >> 7) & 0xFF, eh = (hi >> 7) & 0xFF;
            bool okl = (lo & 0x7FFF) == 0 || (el >= 100 && el <= 140);
            bool okh = (hi & 0x7FFF) == 0 || (eh >= 100 && eh <= 140);
            all_ok &= (okl && okh);
        }
        int cnt = __syncthreads_count(all_ok);
        if (threadIdx.x == 0) g_is_bf16 = (cnt > 128) ? 1 : 0;
    } else if (blockIdx.x == 1) {
        bool bad = false, oddnz = false;
        for (int j = 0; j < 16; j++) {
            int i = threadIdx.x * 16 + j;
            int v = ew[i];
            if (v < 0 || v >= NN)  bad = true;
            if ((i & 1) && v != 0) oddnz = true;
        }
        int cbad = __syncthreads_count(bad);
        int codd = __syncthreads_count(oddnz);
        if (threadIdx.x == 0) {
            g_bad_int     = (cbad > 0) ? 1 : 0;
            g_odd_nonzero = (codd > 0) ? 1 : 0;
        }
    }
}

// ---------------- kernel 2: materialize W (fp16, fragment-swizzled) + a ----
// For W[n][k]: nb=n>>3, g=n&7, ks=k>>4, h=(k>>3)&1, tp=(k&7)>>1, hi=k&1
//   g_wh[ (nb*16+ks)*128 + (g*4+tp)*4 + h*2 + hi ] = fp16(W[n][k])
// B fragment = one LDS.64 (uint2) at uint2-index (nb*16+ks)*32 + lane.
__global__ void fconv_all_kernel(const void* __restrict__ Wraw,
                                 const void* __restrict__ araw) {
    int i = blockIdx.x * blockDim.x + threadIdx.x;
    bool bf = (g_is_bf16 != 0);
    if (i < HDIM * INF) {
        float v = bf ? __bfloat162float(((const __nv_bfloat16*)Wraw)[i])
                     : ((const float*)Wraw)[i];
        int n = i >> 8, k = i & 255;
        int nb = n >> 3, g = n & 7;
        int ks = k >> 4, h = (k >> 3) & 1, tp = (k & 7) >> 1, hi = k & 1;
        int dst = (nb * 16 + ks) * 128 + (g * 4 + tp) * 4 + h * 2 + hi;
        g_wh[dst] = __float2half_rn(v);
    } else if (i < HDIM * INF + 2 * OUTF) {
        int j = i - HDIM * INF;
        float v = bf ? __bfloat162float(((const __nv_bfloat16*)araw)[j])
                     : ((const float*)araw)[j];
        g_af[j] = v;
    }
}

// ---------------- kernel 3: convert x -> fp16 (8 elements/thread) ----------
__global__ void convert_x_kernel(const void* __restrict__ xraw) {
    int gid = blockIdx.x * blockDim.x + threadIdx.x;
    if (gid >= NROWS * INF / 8) return;
    __half2 h[4];
    if (g_is_bf16 == 0) {
        const float4* xp = (const float4*)xraw + (size_t)gid * 2;
        float4 f0 = __ldg(xp);
        float4 f1 = __ldg(xp + 1);
        h[0] = __floats2half2_rn(f0.x, f0.y);
        h[1] = __floats2half2_rn(f0.z, f0.w);
        h[2] = __floats2half2_rn(f1.x, f1.y);
        h[3] = __floats2half2_rn(f1.z, f1.w);
    } else {
        uint4 u = __ldg((const uint4*)xraw + gid);
        const __nv_bfloat162* b = (const __nv_bfloat162*)&u;
        #pragma unroll
        for (int j = 0; j < 4; j++) {
            float2 f = __bfloat1622float2(b[j]);
            h[j] = __floats2half2_rn(f.x, f.y);
        }
    }
    ((uint4*)g_xh)[gid] = *(uint4*)h;
}

// ---------------- kernel 4: convert indices + last-edge (fused) ------------
__global__ void convert_lastedge_kernel(const void* __restrict__ raw) {
    int e = blockIdx.x * blockDim.x + threadIdx.x;
    if (e >= EE) return;
    int s, d;
    if (g_bad_int) {                 // float32 layout
        const float* p = (const float*)raw;
        s = (int)p[e];  d = (int)p[EE + e];
    } else if (g_odd_nonzero) {      // int32 layout
        const int* p = (const int*)raw;
        s = p[e];       d = p[EE + e];
    } else {                         // int64 layout
        const long long* p = (const long long*)raw;
        s = (int)p[e];  d = (int)p[EE + e];
    }
    s = min(max(s, 0), NN - 1);
    d = min(max(d, 0), NN - 1);
    g_src[e] = s;
    g_dst[e] = d;
    atomicMax(&g_last[s], e);
}

// ---------------- kernel 5: 4-stage BK=16 fp16 GEMM ------------------------
// BM=128 x BN=128, grid 313. mma.m16n8k16.f16, fp32 accum. 16 iterations.
// Per warp per iter: 8 LDS.32 (A) + 8 LDS.64 (B) + 16 MMA. Single barrier.
// A smem stride 24 halves (48B): bank (12g+t) mod 32 bijective -> conflict-free.
#define BM 128
#define NSTAGE 4
#define ASTH 24
__global__ __launch_bounds__(256, 2) void gemm_fp16(int dummy) {
    __shared__ __half As[NSTAGE][BM * ASTH];   // 4 x 6144 B
    __shared__ uint2  Bs[NSTAGE][512];         // 4 x 4096 B  (total 40 KB)

    const int tid  = threadIdx.x;
    const int lane = tid & 31;
    const int g    = lane >> 2;
    const int t    = lane & 3;
    const int warp = tid >> 5;
    const int wm   = warp & 3;         // 32-row band
    const int wn   = warp >> 2;        // 64-col half
    const int m0   = blockIdx.x * BM;

    float acc[2][8][4];
    #pragma unroll
    for (int i = 0; i < 2; i++)
        #pragma unroll
        for (int j = 0; j < 8; j++)
            #pragma unroll
            for (int q = 0; q < 4; q++) acc[i][j][q] = 0.0f;

    auto issue_tile = [&](int ks, int buf) {
        {   // B tile: 16 nb x 256B = 4 KB; one 16B chunk per thread
            int nb    = tid >> 4;          // 0..15
            int off16 = tid & 15;          // 0..15
            uint32_t d = (uint32_t)__cvta_generic_to_shared(
                (char*)&Bs[buf][0] + nb * 256 + off16 * 16);
            CP_ASYNC16(d, (const char*)g_wh +
                       (((size_t)(nb * 16 + ks)) * 128 + off16 * 8) * 2);
        }
        {   // A tile: 128 rows x 32B = 4 KB; one 16B chunk per thread
            int r = tid >> 1;
            int c = (tid & 1) * 8;         // halves offset 0 or 8
            int row = min(m0 + r, NROWS - 1);
            uint32_t d = (uint32_t)__cvta_generic_to_shared(
                &As[buf][r * ASTH + c]);
            CP_ASYNC16(d, g_xh + (size_t)row * INF + ks * 16 + c);
        }
        CP_COMMIT();
    };

    issue_tile(0, 0);
    issue_tile(1, 1);
    issue_tile(2, 2);

    #pragma unroll 4
    for (int i = 0; i < INF / 16; i++) {      // 16 iterations
        CP_WAIT(2);
        __syncthreads();
        if (i + 3 < INF / 16) issue_tile(i + 3, (i + 3) & (NSTAGE - 1));

        int buf = i & (NSTAGE - 1);
        uint32_t a[2][4];
        #pragma unroll
        for (int mq = 0; mq < 2; mq++) {
            const __half* ap = &As[buf][(wm * 32 + mq * 16 + g) * ASTH];
            a[mq][0] = *(const uint32_t*)(ap + 2 * t);             // (g,   2t..)
            a[mq][1] = *(const uint32_t*)(ap + 8 * ASTH + 2 * t);  // (g+8, 2t..)
            a[mq][2] = *(const uint32_t*)(ap + 8 + 2 * t);         // (g,   8+2t..)
            a[mq][3] = *(const uint32_t*)(ap + 8 * ASTH + 8 + 2 * t);
        }
        #pragma unroll
        for (int nt = 0; nt < 8; nt++) {
            uint2 bb = Bs[buf][(wn * 8 + nt) * 32 + lane];
            #pragma unroll
            for (int mq = 0; mq < 2; mq++) {
                asm volatile(
                    "mma.sync.aligned.m16n8k16.row.col.f32.f16.f16.f32 "
                    "{%0,%1,%2,%3}, {%4,%5,%6,%7}, {%8,%9}, {%0,%1,%2,%3};"
                    : "+f"(acc[mq][nt][0]), "+f"(acc[mq][nt][1]),
                      "+f"(acc[mq][nt][2]), "+f"(acc[mq][nt][3])
                    : "r"(a[mq][0]), "r"(a[mq][1]), "r"(a[mq][2]),
                      "r"(a[mq][3]), "r"(bb.x), "r"(bb.y));
            }
        }
        // no trailing barrier: next write target (i+4)&3 was freed by the
        // readers that passed this iteration's top barrier.
    }

    // Epilogue: fp16 h + fused score dots.
    // D frag: c0=(g,2t) c1=(g,2t+1) c2=(g+8,2t) c3=(g+8,2t+1).
    float ss[2][4], sd[2][4];   // [local head][mq*2 + (0:row g, 1:row g+8)]
    #pragma unroll
    for (int i = 0; i < 2; i++)
        #pragma unroll
        for (int j = 0; j < 4; j++) { ss[i][j] = 0.f; sd[i][j] = 0.f; }

    #pragma unroll
    for (int mq = 0; mq < 2; mq++) {
        int mrow = m0 + wm * 32 + mq * 16 + g;
        #pragma unroll
        for (int nt = 0; nt < 8; nt++) {
            int hl = nt >> 2;
            int fl = (nt & 3) * 8 + 2 * t;
            int ncol = wn * 64 + nt * 8 + 2 * t;
            if (mrow < NROWS)
                *(__half2*)&g_h[(size_t)mrow * HDIM + ncol] =
                    __floats2half2_rn(acc[mq][nt][0], acc[mq][nt][1]);
            if (mrow + 8 < NROWS)
                *(__half2*)&g_h[(size_t)(mrow + 8) * HDIM + ncol] =
                    __floats2half2_rn(acc[mq][nt][2], acc[mq][nt][3]);
            float a0s = g_af[fl],        a1s = g_af[fl + 1];
            float a0d = g_af[OUTF + fl], a1d = g_af[OUTF + fl + 1];
            ss[hl][mq*2+0] += acc[mq][nt][0] * a0s + acc[mq][nt][1] * a1s;
            ss[hl][mq*2+1] += acc[mq][nt][2] * a0s + acc[mq][nt][3] * a1s;
            sd[hl][mq*2+0] += acc[mq][nt][0] * a0d + acc[mq][nt][1] * a1d;
            sd[hl][mq*2+1] += acc[mq][nt][2] * a0d + acc[mq][nt][3] * a1d;
        }
    }
    #pragma unroll
    for (int off = 1; off < 4; off <<= 1) {
        #pragma unroll
        for (int i = 0; i < 2; i++)
            #pragma unroll
            for (int j = 0; j < 4; j++) {
                ss[i][j] += __shfl_xor_sync(0xffffffffu, ss[i][j], off);
                sd[i][j] += __shfl_xor_sync(0xffffffffu, sd[i][j], off);
            }
    }
    if (t == 0) {
        #pragma unroll
        for (int hl = 0; hl < 2; hl++) {
            int head = wn * 2 + hl;
            #pragma unroll
            for (int mq = 0; mq < 2; mq++)
                #pragma unroll
                for (int rr = 0; rr < 2; rr++) {
                    int row = m0 + wm * 32 + mq * 16 + g + rr * 8;
                    if (row < NROWS) {
                        g_ssrc[row * HEADS + head] = ss[hl][mq*2+rr];
                        g_sdst[row * HEADS + head] = sd[hl][mq*2+rr];
                    }
                }
        }
    }
}

// ---------------- kernel 6: aw from last-edge softmax over batch -----------
__global__ void aw_kernel() {
    int gid = blockIdx.x * blockDim.x + threadIdx.x;   // n*HEADS + h
    if (gid >= NN * HEADS) return;
    int hh = gid & (HEADS - 1);
    int n  = gid >> 2;
    int e  = g_last[n];
    float w0 = 0.0f, w1 = 0.0f;
    if (e >= 0) {
        int d = g_dst[e];
        float z0 = g_ssrc[n * HEADS + hh]        + g_sdst[d * HEADS + hh];
        float z1 = g_ssrc[(NN + n) * HEADS + hh] + g_sdst[(NN + d) * HEADS + hh];
        z0 = z0 > 0.0f ? z0 : NEG_SLOPE * z0;
        z1 = z1 > 0.0f ? z1 : NEG_SLOPE * z1;
        float m  = fmaxf(z0, z1);
        float p0 = __expf(z0 - m);
        float p1 = __expf(z1 - m);
        float inv = 1.0f / (p0 + p1);
        w0 = p0 * inv;
        w1 = p1 * inv;
    }
    g_aw[n * HEADS + hh]        = 0.25f * w0;   // fold head-mean
    g_aw[(NN + n) * HEADS + hh] = 0.25f * w1;
}

// ---------------- kernel 7: aggregation, both batches per thread -----------
__device__ __forceinline__ void red_add_v4(float* ptr, float4 v) {
    asm volatile("red.global.add.v4.f32 [%0], {%1, %2, %3, %4};"
                 :: "l"(ptr), "f"(v.x), "f"(v.y), "f"(v.z), "f"(v.w)
                 : "memory");
}

__device__ __forceinline__ float4 ldh4(const __half* p) {
    uint2 u = __ldg((const uint2*)p);
    float2 a = __half22float2(*(__half2*)&u.x);
    float2 b = __half22float2(*(__half2*)&u.y);
    return make_float4(a.x, a.y, b.x, b.y);
}

__global__ __launch_bounds__(256) void agg_kernel(float* __restrict__ out) {
    int gid = blockIdx.x * blockDim.x + threadIdx.x;
    if (gid >= EE * (OUTF / 4)) return;
    int f4 = gid & 7;          // 0..7
    int e  = gid >> 3;

    int src = g_src[e];
    int dst = g_dst[e];

    float4 c0 = *(const float4*)(g_aw + (size_t)src * HEADS);
    float4 c1 = *(const float4*)(g_aw + ((size_t)NN + src) * HEADS);

    const __half* hp0 = g_h + (size_t)dst * HDIM + f4 * 4;
    const __half* hp1 = hp0 + (size_t)NN * HDIM;
    float4 h00 = ldh4(hp0);
    float4 h01 = ldh4(hp0 + OUTF);
    float4 h02 = ldh4(hp0 + 2 * OUTF);
    float4 h03 = ldh4(hp0 + 3 * OUTF);
    float4 h10 = ldh4(hp1);
    float4 h11 = ldh4(hp1 + OUTF);
    float4 h12 = ldh4(hp1 + 2 * OUTF);
    float4 h13 = ldh4(hp1 + 3 * OUTF);

    float4 v0, v1;
    v0.x = c0.x * h00.x + c0.y * h01.x + c0.z * h02.x + c0.w * h03.x;
    v0.y = c0.x * h00.y + c0.y * h01.y + c0.z * h02.y + c0.w * h03.y;
    v0.z = c0.x * h00.z + c0.y * h01.z + c0.z * h02.z + c0.w * h03.z;
    v0.w = c0.x * h00.w + c0.y * h01.w + c0.z * h02.w + c0.w * h03.w;
    v1.x = c1.x * h10.x + c1.y * h11.x + c1.z * h12.x + c1.w * h13.x;
    v1.y = c1.x * h10.y + c1.y * h11.y + c1.z * h12.y + c1.w * h13.y;
    v1.z = c1.x * h10.z + c1.y * h11.z + c1.z * h12.z + c1.w * h13.z;
    v1.w = c1.x * h10.w + c1.y * h11.w + c1.z * h12.w + c1.w * h13.w;

    red_add_v4(out + (size_t)src * OUTF + f4 * 4, v0);
    red_add_v4(out + ((size_t)NN + src) * OUTF + f4 * 4, v1);
}

// ---------------- launch ---------------------------------------------------
extern "C" void kernel_launch(void* const* d_in, const int* in_sizes, int n_in,
                              void* d_out, int out_size) {
    // Rank-based binding: largest -> x, 2nd -> edges, 3rd -> W, smallest -> a
    int order[8];
    int m = n_in < 8 ? n_in : 8;
    for (int i = 0; i < m; i++) order[i] = i;
    for (int i = 0; i < m; i++)
        for (int j = i + 1; j < m; j++)
            if (in_sizes[order[j]] > in_sizes[order[i]]) {
                int t = order[i]; order[i] = order[j]; order[j] = t;
            }
    const void* x  = d_in[m > 0 ? order[0] : 0];
    const void* ei = d_in[m > 1 ? order[1] : 1];
    const void* W  = d_in[m > 2 ? order[2] : 2];
    const void* a  = d_in[m > 3 ? order[3] : 3];

    float* out = (float*)d_out;

    {
        int n = out_size > NN ? out_size : NN;
        init_probe_kernel<<<(n + 255) / 256, 256>>>(out, out_size,
                             (const unsigned*)x, (const int*)ei);         // 1
    }
    fconv_all_kernel<<<(HDIM * INF + 2 * OUTF + 255) / 256, 256>>>(W, a); // 2
    convert_x_kernel<<<(NROWS * INF / 8 + 255) / 256, 256>>>(x);          // 3
    gemm_fp16<<<(NROWS + BM - 1) / BM, 256>>>(0);                         // 4 <- profiled
    convert_lastedge_kernel<<<(EE + 255) / 256, 256>>>(ei);               // 5
    aw_kernel<<<(NN * HEADS + 255) / 256, 256>>>();                       // 6
    agg_kernel<<<(EE * (OUTF / 4) + 255) / 256, 256>>>(out);              // 7
}